// round 2
// baseline (speedup 1.0000x reference)
#include <cuda_runtime.h>
#include <cuda_bf16.h>

#define SQL 2048
#define DMODEL 1024
#define NB 2
#define NH 16
#define HDIM 64

// Scratch (allocation-free rule: __device__ globals)
__device__ float g_qh[(size_t)NB * SQL * DMODEL];
__device__ float g_k [(size_t)NB * SQL * DMODEL];
__device__ float g_v [(size_t)NB * SQL * DMODEL];

// ---------------------------------------------------------------------------
// Generic 128x128x8 register-tiled fp32 GEMM with optional split output.
// C = A[M,K] @ B[K,N].  If C1 != nullptr, cols >= halfN go to C1 (width halfN),
// cols < halfN go to C0 (width halfN).  Otherwise C0 has width halfN (= N).
// Register prefetch of the next K-tile hides global-load latency.
// ---------------------------------------------------------------------------
__global__ __launch_bounds__(256) void gemm128(
    const float* __restrict__ A, const float* __restrict__ Bm,
    float* __restrict__ C0, float* __restrict__ C1,
    int M, int N, int K, int halfN)
{
    __shared__ float smA[8][128];   // transposed A tile: [k][row]
    __shared__ float smB[8][128];   // B tile: [k][col]

    int t  = threadIdx.x;
    int ty = t >> 4, tx = t & 15;
    int brow = blockIdx.y * 128, bcol = blockIdx.x * 128;

    float acc[8][8];
    #pragma unroll
    for (int i = 0; i < 8; i++)
        #pragma unroll
        for (int j = 0; j < 8; j++) acc[i][j] = 0.0f;

    const float* Aptr = A + (size_t)(brow + (t >> 1)) * K + ((t & 1) * 4);
    const float* Bptr = Bm + (size_t)(t >> 5) * N + bcol + (t & 31) * 4;

    // prefetch first tile
    float4 a4 = *(const float4*)(Aptr);
    float4 b4 = *(const float4*)(Bptr);

    for (int k0 = 0; k0 < K; k0 += 8) {
        __syncthreads();
        // stage current tile
        {
            int ar = t >> 1, ak = (t & 1) * 4;
            smA[ak + 0][ar] = a4.x; smA[ak + 1][ar] = a4.y;
            smA[ak + 2][ar] = a4.z; smA[ak + 3][ar] = a4.w;
            *(float4*)&smB[t >> 5][(t & 31) * 4] = b4;
        }
        __syncthreads();
        // prefetch next tile (overlaps with FFMA below)
        if (k0 + 8 < K) {
            a4 = *(const float4*)(Aptr + (k0 + 8));
            b4 = *(const float4*)(Bptr + (size_t)(k0 + 8) * N);
        }
        #pragma unroll
        for (int kk = 0; kk < 8; kk++) {
            float a[8], b[8];
            *(float4*)&a[0] = *(const float4*)&smA[kk][8 * ty];
            *(float4*)&a[4] = *(const float4*)&smA[kk][8 * ty + 4];
            *(float4*)&b[0] = *(const float4*)&smB[kk][8 * tx];
            *(float4*)&b[4] = *(const float4*)&smB[kk][8 * tx + 4];
            #pragma unroll
            for (int i = 0; i < 8; i++)
                #pragma unroll
                for (int j = 0; j < 8; j++)
                    acc[i][j] += a[i] * b[j];
        }
    }

    #pragma unroll
    for (int i = 0; i < 8; i++) {
        int row = brow + 8 * ty + i;
        #pragma unroll
        for (int jg = 0; jg < 8; jg += 4) {
            int col = bcol + 8 * tx + jg;
            float4 val = make_float4(acc[i][jg], acc[i][jg + 1],
                                     acc[i][jg + 2], acc[i][jg + 3]);
            if (C1 && col >= halfN)
                *(float4*)(C1 + (size_t)row * halfN + (col - halfN)) = val;
            else
                *(float4*)(C0 + (size_t)row * halfN + col) = val;
        }
    }
}

// ---------------------------------------------------------------------------
// LayerNorm over last dim (64) per head.  One warp per 64-element row.
// ---------------------------------------------------------------------------
__global__ __launch_bounds__(256) void ln64(
    float* __restrict__ v, const float* __restrict__ gamma,
    const float* __restrict__ beta)
{
    int lane = threadIdx.x & 31;
    size_t row = (size_t)blockIdx.x * (blockDim.x >> 5) + (threadIdx.x >> 5);
    float* p = v + row * HDIM;
    float x0 = p[lane], x1 = p[lane + 32];
    float s  = x0 + x1;
    float ss = x0 * x0 + x1 * x1;
    #pragma unroll
    for (int o = 16; o > 0; o >>= 1) {
        s  += __shfl_xor_sync(0xffffffffu, s,  o);
        ss += __shfl_xor_sync(0xffffffffu, ss, o);
    }
    float mu  = s * (1.0f / HDIM);
    float var = ss * (1.0f / HDIM) - mu * mu;
    float r   = rsqrtf(var + 1e-5f);
    p[lane]      = (x0 - mu) * r * gamma[lane]      + beta[lane];
    p[lane + 32] = (x1 - mu) * r * gamma[lane + 32] + beta[lane + 32];
}

// ---------------------------------------------------------------------------
// Flash-style sigmoid attention.  64 q-rows per block, kv tiles of 64,
// causal tile skipping (tiles j in [0, qb]).  Thread (ty,tx) in 16x16 holds a
// 4x4 micro-tile of S and of O.  Q and K stored transposed [d][row] in smem
// for conflict-free float4 reads; V row-major; S staged in smem for the
// second matmul.  3 x 16KB smem = exactly 48KB -> 2 CTAs/SM.
// ---------------------------------------------------------------------------
__global__ __launch_bounds__(256) void attn64(
    const float* __restrict__ qh, const float* __restrict__ kb,
    const float* __restrict__ vb, float* __restrict__ out)
{
    __shared__ float smQT[64][64];   // Q^T : [d][r]
    __shared__ float smKV[64][64];   // K^T : [d][c]   then  V : [c][d]
    __shared__ float smS [64][64];   // S   : [r][c]

    int t  = threadIdx.x;
    int ty = t >> 4, tx = t & 15;
    int qb = blockIdx.x, h = blockIdx.y, b = blockIdx.z;
    int q0 = qb * 64;

    const float* Qb = qh + ((size_t)(b * SQL + q0)) * DMODEL + h * HDIM;
    const float* Kb = kb + ((size_t)b * SQL) * DMODEL + h * HDIM;
    const float* Vb = vb + ((size_t)b * SQL) * DMODEL + h * HDIM;

    // load Q tile transposed
    {
        int row = t >> 2;
        int cg  = (t & 3) * 16;
        const float* src = Qb + (size_t)row * DMODEL + cg;
        #pragma unroll
        for (int i = 0; i < 4; i++) {
            float4 v4 = *(const float4*)(src + i * 4);
            int d = cg + i * 4;
            smQT[d + 0][row] = v4.x; smQT[d + 1][row] = v4.y;
            smQT[d + 2][row] = v4.z; smQT[d + 3][row] = v4.w;
        }
    }

    float acc[4][4];
    #pragma unroll
    for (int i = 0; i < 4; i++)
        #pragma unroll
        for (int j = 0; j < 4; j++) acc[i][j] = 0.0f;

    for (int j = 0; j <= qb; j++) {
        int k0 = j * 64;
        __syncthreads();   // prev O-phase done reading smKV/smS; Q visible
        // load K tile transposed
        {
            int row = t >> 2;
            int cg  = (t & 3) * 16;
            const float* src = Kb + (size_t)(k0 + row) * DMODEL + cg;
            #pragma unroll
            for (int i = 0; i < 4; i++) {
                float4 v4 = *(const float4*)(src + i * 4);
                int d = cg + i * 4;
                smKV[d + 0][row] = v4.x; smKV[d + 1][row] = v4.y;
                smKV[d + 2][row] = v4.z; smKV[d + 3][row] = v4.w;
            }
        }
        __syncthreads();
        // S = Q K^T
        float s[4][4];
        #pragma unroll
        for (int i = 0; i < 4; i++)
            #pragma unroll
            for (int jj = 0; jj < 4; jj++) s[i][jj] = 0.0f;
        #pragma unroll
        for (int d = 0; d < 64; d++) {
            float a[4], bb[4];
            *(float4*)a  = *(const float4*)&smQT[d][4 * ty];
            *(float4*)bb = *(const float4*)&smKV[d][4 * tx];
            #pragma unroll
            for (int i = 0; i < 4; i++)
                #pragma unroll
                for (int jj = 0; jj < 4; jj++)
                    s[i][jj] += a[i] * bb[jj];
        }
        // sigmoid + causal mask -> smS
        #pragma unroll
        for (int i = 0; i < 4; i++) {
            int qi = q0 + 4 * ty + i;
            float tmp[4];
            #pragma unroll
            for (int jj = 0; jj < 4; jj++) {
                int kj = k0 + 4 * tx + jj;
                float x = s[i][jj] * 0.125f - 8.0f;     // scale^2 = HD^-0.5, bias
                float sig = 1.0f / (1.0f + __expf(-x));
                tmp[jj] = (kj <= qi) ? sig : 0.0f;
            }
            *(float4*)&smS[4 * ty + i][4 * tx] =
                make_float4(tmp[0], tmp[1], tmp[2], tmp[3]);
        }
        __syncthreads();   // K reads done, S written
        // load V tile (row-major), overwriting K
        {
            int row = t >> 2;
            int cg  = (t & 3) * 16;
            const float* src = Vb + (size_t)(k0 + row) * DMODEL + cg;
            #pragma unroll
            for (int i = 0; i < 4; i++)
                *(float4*)&smKV[row][cg + i * 4] = *(const float4*)(src + i * 4);
        }
        __syncthreads();
        // O += S V
        #pragma unroll
        for (int c = 0; c < 64; c++) {
            float vv[4], sv[4];
            *(float4*)vv = *(const float4*)&smKV[c][4 * tx];
            #pragma unroll
            for (int i = 0; i < 4; i++) sv[i] = smS[4 * ty + i][c];
            #pragma unroll
            for (int i = 0; i < 4; i++)
                #pragma unroll
                for (int jj = 0; jj < 4; jj++)
                    acc[i][jj] += sv[i] * vv[jj];
        }
    }

    float* ob = out + ((size_t)(b * SQL + q0)) * DMODEL + h * HDIM;
    #pragma unroll
    for (int i = 0; i < 4; i++)
        *(float4*)(ob + (size_t)(4 * ty + i) * DMODEL + 4 * tx) =
            make_float4(acc[i][0], acc[i][1], acc[i][2], acc[i][3]);
}

// ---------------------------------------------------------------------------
extern "C" void kernel_launch(void* const* d_in, const int* in_sizes, int n_in,
                              void* d_out, int out_size)
{
    const float* q     = (const float*)d_in[0];
    const float* kv    = (const float*)d_in[1];
    const float* Wq    = (const float*)d_in[2];
    const float* Wkv   = (const float*)d_in[3];
    const float* gamma = (const float*)d_in[4];
    const float* beta  = (const float*)d_in[5];
    const float* Wproj = (const float*)d_in[6];
    float* out = (float*)d_out;

    float *qh, *kbuf, *vbuf;
    cudaGetSymbolAddress((void**)&qh,   g_qh);
    cudaGetSymbolAddress((void**)&kbuf, g_k);
    cudaGetSymbolAddress((void**)&vbuf, g_v);

    const int M = NB * SQL;   // 4096

    // 1) qh = q @ Wq
    gemm128<<<dim3(DMODEL / 128, M / 128), 256>>>(
        q, Wq, qh, nullptr, M, DMODEL, DMODEL, DMODEL);

    // 2) kvh = kv @ Wkv, split into K (cols < 1024) and V (cols >= 1024)
    gemm128<<<dim3(2 * DMODEL / 128, M / 128), 256>>>(
        kv, Wkv, kbuf, vbuf, M, 2 * DMODEL, DMODEL, DMODEL);

    // 3) per-head LayerNorm of V
    ln64<<<(NB * SQL * NH) / 8, 256>>>(vbuf, gamma, beta);

    // 4) attention -> attn_times_v (first half of d_out)
    attn64<<<dim3(SQL / 64, NH, NB), 256>>>(qh, kbuf, vbuf, out);

    // 5) attn_proj = attn_times_v @ Wproj (second half of d_out)
    gemm128<<<dim3(DMODEL / 128, M / 128), 256>>>(
        out, Wproj, out + (size_t)M * DMODEL, nullptr, M, DMODEL, DMODEL, DMODEL);
}

// round 3
// speedup vs baseline: 1.5551x; 1.5551x over previous
#include <cuda_runtime.h>
#include <cuda_bf16.h>

#define SQL 2048
#define DMODEL 1024
#define NB 2
#define NH 16
#define HDIM 64

// Scratch (allocation-free rule: __device__ globals)
__device__ float g_qh[(size_t)NB * SQL * DMODEL];
__device__ float g_k [(size_t)NB * SQL * DMODEL];
__device__ float g_v [(size_t)NB * SQL * DMODEL];

// ---------------------------------------------------------------------------
// tf32 helpers
// ---------------------------------------------------------------------------
__device__ __forceinline__ float f2tf32(float x) {
    unsigned u;
    asm("cvt.rna.tf32.f32 %0, %1;" : "=r"(u) : "f"(x));
    return __uint_as_float(u);
}

__device__ __forceinline__ void mma_tf32(
    float* c, const unsigned* a, const unsigned* b)
{
    asm volatile(
        "mma.sync.aligned.m16n8k8.row.col.f32.tf32.tf32.f32 "
        "{%0,%1,%2,%3}, {%4,%5,%6,%7}, {%8,%9}, {%0,%1,%2,%3};"
        : "+f"(c[0]), "+f"(c[1]), "+f"(c[2]), "+f"(c[3])
        : "r"(a[0]), "r"(a[1]), "r"(a[2]), "r"(a[3]),
          "r"(b[0]), "r"(b[1]));
}

// ---------------------------------------------------------------------------
// tf32 tensor-core GEMM, 128x128x16 tile, 8 warps (64x32 warp-tile each).
// C = A[M,K] @ B[K,N].  If C1 != nullptr, cols >= halfN go to C1 (width
// halfN), cols < halfN go to C0 (width halfN).  Otherwise C0 has width
// halfN (= N).  Register prefetch of next K-tile; smem row pads (20 / 136
// floats) give conflict-free fragment loads.
// ---------------------------------------------------------------------------
__global__ __launch_bounds__(256) void gemm_tc(
    const float* __restrict__ A, const float* __restrict__ Bm,
    float* __restrict__ C0, float* __restrict__ C1,
    int M, int N, int K, int halfN)
{
    __shared__ float sA[128][20];    // [row][k]  (pad 16 -> 20)
    __shared__ float sB[16][136];    // [k][col]  (pad 128 -> 136)

    int t    = threadIdx.x;
    int lane = t & 31;
    int warp = t >> 5;
    int wm   = warp >> 2;            // 0..1  (m)
    int wn   = warp & 3;             // 0..3  (n)
    int brow = blockIdx.y * 128, bcol = blockIdx.x * 128;

    float acc[4][4][4];
    #pragma unroll
    for (int mi = 0; mi < 4; mi++)
        #pragma unroll
        for (int ni = 0; ni < 4; ni++)
            #pragma unroll
            for (int r = 0; r < 4; r++) acc[mi][ni][r] = 0.0f;

    // global-load addressing:
    //  A tile 128x16 = 512 float4:  id -> row=id>>2, colgrp=id&3
    //  B tile 16x128 = 512 float4:  id -> row=id>>5, colgrp=id&31
    const float* Ap0 = A + (size_t)(brow + (t >> 2)) * K + (t & 3) * 4;
    const float* Ap1 = Ap0 + (size_t)64 * K;
    const float* Bp0 = Bm + (size_t)(t >> 5) * N + bcol + (t & 31) * 4;
    const float* Bp1 = Bp0 + (size_t)8 * N;

    float4 a40 = *(const float4*)(Ap0);
    float4 a41 = *(const float4*)(Ap1);
    float4 b40 = *(const float4*)(Bp0);
    float4 b41 = *(const float4*)(Bp1);

    int arow = t >> 2,  acg = (t & 3) * 4;
    int bk   = t >> 5,  bcg = (t & 31) * 4;

    for (int k0 = 0; k0 < K; k0 += 16) {
        __syncthreads();
        // stage current tile (convert to tf32 bit patterns)
        {
            float4 v;
            v = make_float4(f2tf32(a40.x), f2tf32(a40.y), f2tf32(a40.z), f2tf32(a40.w));
            *(float4*)&sA[arow][acg] = v;
            v = make_float4(f2tf32(a41.x), f2tf32(a41.y), f2tf32(a41.z), f2tf32(a41.w));
            *(float4*)&sA[arow + 64][acg] = v;
            v = make_float4(f2tf32(b40.x), f2tf32(b40.y), f2tf32(b40.z), f2tf32(b40.w));
            *(float4*)&sB[bk][bcg] = v;
            v = make_float4(f2tf32(b41.x), f2tf32(b41.y), f2tf32(b41.z), f2tf32(b41.w));
            *(float4*)&sB[bk + 8][bcg] = v;
        }
        __syncthreads();
        // prefetch next tile (overlaps with tensor math below)
        if (k0 + 16 < K) {
            a40 = *(const float4*)(Ap0 + (k0 + 16));
            a41 = *(const float4*)(Ap1 + (k0 + 16));
            b40 = *(const float4*)(Bp0 + (size_t)(k0 + 16) * N);
            b41 = *(const float4*)(Bp1 + (size_t)(k0 + 16) * N);
        }
        #pragma unroll
        for (int ks = 0; ks < 16; ks += 8) {
            unsigned af[4][4];
            #pragma unroll
            for (int mi = 0; mi < 4; mi++) {
                int r = wm * 64 + mi * 16 + (lane >> 2);
                int c = ks + (lane & 3);
                af[mi][0] = __float_as_uint(sA[r][c]);
                af[mi][1] = __float_as_uint(sA[r + 8][c]);
                af[mi][2] = __float_as_uint(sA[r][c + 4]);
                af[mi][3] = __float_as_uint(sA[r + 8][c + 4]);
            }
            unsigned bf[4][2];
            #pragma unroll
            for (int ni = 0; ni < 4; ni++) {
                int cb = wn * 32 + ni * 8 + (lane >> 2);
                int kr = ks + (lane & 3);
                bf[ni][0] = __float_as_uint(sB[kr][cb]);
                bf[ni][1] = __float_as_uint(sB[kr + 4][cb]);
            }
            #pragma unroll
            for (int mi = 0; mi < 4; mi++)
                #pragma unroll
                for (int ni = 0; ni < 4; ni++)
                    mma_tf32(acc[mi][ni], af[mi], bf[ni]);
        }
    }

    // epilogue: c0,c1 -> (row, col..col+1); c2,c3 -> (row+8, col..col+1)
    #pragma unroll
    for (int mi = 0; mi < 4; mi++) {
        #pragma unroll
        for (int ni = 0; ni < 4; ni++) {
            int row = brow + wm * 64 + mi * 16 + (lane >> 2);
            int col = bcol + wn * 32 + ni * 8 + 2 * (lane & 3);
            float* dst;
            int ccol = col;
            if (C1 && col >= halfN) { dst = C1; ccol = col - halfN; }
            else                    { dst = C0; }
            *(float2*)(dst + (size_t)row * halfN + ccol) =
                make_float2(acc[mi][ni][0], acc[mi][ni][1]);
            *(float2*)(dst + (size_t)(row + 8) * halfN + ccol) =
                make_float2(acc[mi][ni][2], acc[mi][ni][3]);
        }
    }
}

// ---------------------------------------------------------------------------
// LayerNorm over last dim (64) per head.  One warp per 64-element row.
// ---------------------------------------------------------------------------
__global__ __launch_bounds__(256) void ln64(
    float* __restrict__ v, const float* __restrict__ gamma,
    const float* __restrict__ beta)
{
    int lane = threadIdx.x & 31;
    size_t row = (size_t)blockIdx.x * (blockDim.x >> 5) + (threadIdx.x >> 5);
    float* p = v + row * HDIM;
    float x0 = p[lane], x1 = p[lane + 32];
    float s  = x0 + x1;
    float ss = x0 * x0 + x1 * x1;
    #pragma unroll
    for (int o = 16; o > 0; o >>= 1) {
        s  += __shfl_xor_sync(0xffffffffu, s,  o);
        ss += __shfl_xor_sync(0xffffffffu, ss, o);
    }
    float mu  = s * (1.0f / HDIM);
    float var = ss * (1.0f / HDIM) - mu * mu;
    float r   = rsqrtf(var + 1e-5f);
    p[lane]      = (x0 - mu) * r * gamma[lane]      + beta[lane];
    p[lane + 32] = (x1 - mu) * r * gamma[lane + 32] + beta[lane + 32];
}

// ---------------------------------------------------------------------------
// Flash-style sigmoid attention (fp32 SIMT; round-3 target for mma).
// ---------------------------------------------------------------------------
__global__ __launch_bounds__(256) void attn64(
    const float* __restrict__ qh, const float* __restrict__ kb,
    const float* __restrict__ vb, float* __restrict__ out)
{
    __shared__ float smQT[64][64];   // Q^T : [d][r]
    __shared__ float smKV[64][64];   // K^T : [d][c]   then  V : [c][d]
    __shared__ float smS [64][64];   // S   : [r][c]

    int t  = threadIdx.x;
    int ty = t >> 4, tx = t & 15;
    int qb = blockIdx.x, h = blockIdx.y, b = blockIdx.z;
    int q0 = qb * 64;

    const float* Qb = qh + ((size_t)(b * SQL + q0)) * DMODEL + h * HDIM;
    const float* Kb = kb + ((size_t)b * SQL) * DMODEL + h * HDIM;
    const float* Vb = vb + ((size_t)b * SQL) * DMODEL + h * HDIM;

    // load Q tile transposed
    {
        int row = t >> 2;
        int cg  = (t & 3) * 16;
        const float* src = Qb + (size_t)row * DMODEL + cg;
        #pragma unroll
        for (int i = 0; i < 4; i++) {
            float4 v4 = *(const float4*)(src + i * 4);
            int d = cg + i * 4;
            smQT[d + 0][row] = v4.x; smQT[d + 1][row] = v4.y;
            smQT[d + 2][row] = v4.z; smQT[d + 3][row] = v4.w;
        }
    }

    float acc[4][4];
    #pragma unroll
    for (int i = 0; i < 4; i++)
        #pragma unroll
        for (int j = 0; j < 4; j++) acc[i][j] = 0.0f;

    for (int j = 0; j <= qb; j++) {
        int k0 = j * 64;
        __syncthreads();
        // load K tile transposed
        {
            int row = t >> 2;
            int cg  = (t & 3) * 16;
            const float* src = Kb + (size_t)(k0 + row) * DMODEL + cg;
            #pragma unroll
            for (int i = 0; i < 4; i++) {
                float4 v4 = *(const float4*)(src + i * 4);
                int d = cg + i * 4;
                smKV[d + 0][row] = v4.x; smKV[d + 1][row] = v4.y;
                smKV[d + 2][row] = v4.z; smKV[d + 3][row] = v4.w;
            }
        }
        __syncthreads();
        // S = Q K^T
        float s[4][4];
        #pragma unroll
        for (int i = 0; i < 4; i++)
            #pragma unroll
            for (int jj = 0; jj < 4; jj++) s[i][jj] = 0.0f;
        #pragma unroll
        for (int d = 0; d < 64; d++) {
            float a[4], bb[4];
            *(float4*)a  = *(const float4*)&smQT[d][4 * ty];
            *(float4*)bb = *(const float4*)&smKV[d][4 * tx];
            #pragma unroll
            for (int i = 0; i < 4; i++)
                #pragma unroll
                for (int jj = 0; jj < 4; jj++)
                    s[i][jj] += a[i] * bb[jj];
        }
        // sigmoid + causal mask -> smS
        #pragma unroll
        for (int i = 0; i < 4; i++) {
            int qi = q0 + 4 * ty + i;
            float tmp[4];
            #pragma unroll
            for (int jj = 0; jj < 4; jj++) {
                int kj = k0 + 4 * tx + jj;
                float x = s[i][jj] * 0.125f - 8.0f;
                float sig = 1.0f / (1.0f + __expf(-x));
                tmp[jj] = (kj <= qi) ? sig : 0.0f;
            }
            *(float4*)&smS[4 * ty + i][4 * tx] =
                make_float4(tmp[0], tmp[1], tmp[2], tmp[3]);
        }
        __syncthreads();
        // load V tile (row-major), overwriting K
        {
            int row = t >> 2;
            int cg  = (t & 3) * 16;
            const float* src = Vb + (size_t)(k0 + row) * DMODEL + cg;
            #pragma unroll
            for (int i = 0; i < 4; i++)
                *(float4*)&smKV[row][cg + i * 4] = *(const float4*)(src + i * 4);
        }
        __syncthreads();
        // O += S V
        #pragma unroll
        for (int c = 0; c < 64; c++) {
            float vv[4], sv[4];
            *(float4*)vv = *(const float4*)&smKV[c][4 * tx];
            #pragma unroll
            for (int i = 0; i < 4; i++) sv[i] = smS[4 * ty + i][c];
            #pragma unroll
            for (int i = 0; i < 4; i++)
                #pragma unroll
                for (int jj = 0; jj < 4; jj++)
                    acc[i][jj] += sv[i] * vv[jj];
        }
    }

    float* ob = out + ((size_t)(b * SQL + q0)) * DMODEL + h * HDIM;
    #pragma unroll
    for (int i = 0; i < 4; i++)
        *(float4*)(ob + (size_t)(4 * ty + i) * DMODEL + 4 * tx) =
            make_float4(acc[i][0], acc[i][1], acc[i][2], acc[i][3]);
}

// ---------------------------------------------------------------------------
extern "C" void kernel_launch(void* const* d_in, const int* in_sizes, int n_in,
                              void* d_out, int out_size)
{
    const float* q     = (const float*)d_in[0];
    const float* kv    = (const float*)d_in[1];
    const float* Wq    = (const float*)d_in[2];
    const float* Wkv   = (const float*)d_in[3];
    const float* gamma = (const float*)d_in[4];
    const float* beta  = (const float*)d_in[5];
    const float* Wproj = (const float*)d_in[6];
    float* out = (float*)d_out;

    float *qh, *kbuf, *vbuf;
    cudaGetSymbolAddress((void**)&qh,   g_qh);
    cudaGetSymbolAddress((void**)&kbuf, g_k);
    cudaGetSymbolAddress((void**)&vbuf, g_v);

    const int M = NB * SQL;   // 4096

    // 1) qh = q @ Wq
    gemm_tc<<<dim3(DMODEL / 128, M / 128), 256>>>(
        q, Wq, qh, nullptr, M, DMODEL, DMODEL, DMODEL);

    // 2) kvh = kv @ Wkv, split into K (cols < 1024) and V (cols >= 1024)
    gemm_tc<<<dim3(2 * DMODEL / 128, M / 128), 256>>>(
        kv, Wkv, kbuf, vbuf, M, 2 * DMODEL, DMODEL, DMODEL);

    // 3) per-head LayerNorm of V
    ln64<<<(NB * SQL * NH) / 8, 256>>>(vbuf, gamma, beta);

    // 4) attention -> attn_times_v (first half of d_out)
    attn64<<<dim3(SQL / 64, NH, NB), 256>>>(qh, kbuf, vbuf, out);

    // 5) attn_proj = attn_times_v @ Wproj (second half of d_out)
    gemm_tc<<<dim3(DMODEL / 128, M / 128), 256>>>(
        out, Wproj, out + (size_t)M * DMODEL, nullptr, M, DMODEL, DMODEL, DMODEL);
}

// round 4
// speedup vs baseline: 2.6826x; 1.7251x over previous
#include <cuda_runtime.h>
#include <cuda_bf16.h>

#define SQL 2048
#define DMODEL 1024
#define NB 2
#define NH 16
#define HDIM 64

// Scratch (allocation-free rule: __device__ globals)
__device__ float g_qh[(size_t)NB * SQL * DMODEL];
__device__ float g_k [(size_t)NB * SQL * DMODEL];
__device__ float g_v [(size_t)NB * SQL * DMODEL];

// ---------------------------------------------------------------------------
// tf32 helpers
// ---------------------------------------------------------------------------
__device__ __forceinline__ float f2tf32(float x) {
    unsigned u;
    asm("cvt.rna.tf32.f32 %0, %1;" : "=r"(u) : "f"(x));
    return __uint_as_float(u);
}

__device__ __forceinline__ void mma_tf32(
    float* c, const unsigned* a, const unsigned* b)
{
    asm volatile(
        "mma.sync.aligned.m16n8k8.row.col.f32.tf32.tf32.f32 "
        "{%0,%1,%2,%3}, {%4,%5,%6,%7}, {%8,%9}, {%0,%1,%2,%3};"
        : "+f"(c[0]), "+f"(c[1]), "+f"(c[2]), "+f"(c[3])
        : "r"(a[0]), "r"(a[1]), "r"(a[2]), "r"(a[3]),
          "r"(b[0]), "r"(b[1]));
}

// ---------------------------------------------------------------------------
// tf32 tensor-core GEMM, 128x128x16 tile, 8 warps (64x32 warp-tile each).
// C = A[M,K] @ B[K,N].  If C1 != nullptr, cols >= halfN go to C1 (width
// halfN), cols < halfN go to C0 (width halfN).
// ---------------------------------------------------------------------------
__global__ __launch_bounds__(256) void gemm_tc(
    const float* __restrict__ A, const float* __restrict__ Bm,
    float* __restrict__ C0, float* __restrict__ C1,
    int M, int N, int K, int halfN)
{
    __shared__ float sA[128][20];    // [row][k]  (pad 16 -> 20)
    __shared__ float sB[16][136];    // [k][col]  (pad 128 -> 136)

    int t    = threadIdx.x;
    int lane = t & 31;
    int warp = t >> 5;
    int wm   = warp >> 2;
    int wn   = warp & 3;
    int brow = blockIdx.y * 128, bcol = blockIdx.x * 128;

    float acc[4][4][4];
    #pragma unroll
    for (int mi = 0; mi < 4; mi++)
        #pragma unroll
        for (int ni = 0; ni < 4; ni++)
            #pragma unroll
            for (int r = 0; r < 4; r++) acc[mi][ni][r] = 0.0f;

    const float* Ap0 = A + (size_t)(brow + (t >> 2)) * K + (t & 3) * 4;
    const float* Ap1 = Ap0 + (size_t)64 * K;
    const float* Bp0 = Bm + (size_t)(t >> 5) * N + bcol + (t & 31) * 4;
    const float* Bp1 = Bp0 + (size_t)8 * N;

    float4 a40 = *(const float4*)(Ap0);
    float4 a41 = *(const float4*)(Ap1);
    float4 b40 = *(const float4*)(Bp0);
    float4 b41 = *(const float4*)(Bp1);

    int arow = t >> 2,  acg = (t & 3) * 4;
    int bk   = t >> 5,  bcg = (t & 31) * 4;

    for (int k0 = 0; k0 < K; k0 += 16) {
        __syncthreads();
        {
            float4 v;
            v = make_float4(f2tf32(a40.x), f2tf32(a40.y), f2tf32(a40.z), f2tf32(a40.w));
            *(float4*)&sA[arow][acg] = v;
            v = make_float4(f2tf32(a41.x), f2tf32(a41.y), f2tf32(a41.z), f2tf32(a41.w));
            *(float4*)&sA[arow + 64][acg] = v;
            v = make_float4(f2tf32(b40.x), f2tf32(b40.y), f2tf32(b40.z), f2tf32(b40.w));
            *(float4*)&sB[bk][bcg] = v;
            v = make_float4(f2tf32(b41.x), f2tf32(b41.y), f2tf32(b41.z), f2tf32(b41.w));
            *(float4*)&sB[bk + 8][bcg] = v;
        }
        __syncthreads();
        if (k0 + 16 < K) {
            a40 = *(const float4*)(Ap0 + (k0 + 16));
            a41 = *(const float4*)(Ap1 + (k0 + 16));
            b40 = *(const float4*)(Bp0 + (size_t)(k0 + 16) * N);
            b41 = *(const float4*)(Bp1 + (size_t)(k0 + 16) * N);
        }
        #pragma unroll
        for (int ks = 0; ks < 16; ks += 8) {
            unsigned af[4][4];
            #pragma unroll
            for (int mi = 0; mi < 4; mi++) {
                int r = wm * 64 + mi * 16 + (lane >> 2);
                int c = ks + (lane & 3);
                af[mi][0] = __float_as_uint(sA[r][c]);
                af[mi][1] = __float_as_uint(sA[r + 8][c]);
                af[mi][2] = __float_as_uint(sA[r][c + 4]);
                af[mi][3] = __float_as_uint(sA[r + 8][c + 4]);
            }
            unsigned bf[4][2];
            #pragma unroll
            for (int ni = 0; ni < 4; ni++) {
                int cb = wn * 32 + ni * 8 + (lane >> 2);
                int kr = ks + (lane & 3);
                bf[ni][0] = __float_as_uint(sB[kr][cb]);
                bf[ni][1] = __float_as_uint(sB[kr + 4][cb]);
            }
            #pragma unroll
            for (int mi = 0; mi < 4; mi++)
                #pragma unroll
                for (int ni = 0; ni < 4; ni++)
                    mma_tf32(acc[mi][ni], af[mi], bf[ni]);
        }
    }

    #pragma unroll
    for (int mi = 0; mi < 4; mi++) {
        #pragma unroll
        for (int ni = 0; ni < 4; ni++) {
            int row = brow + wm * 64 + mi * 16 + (lane >> 2);
            int col = bcol + wn * 32 + ni * 8 + 2 * (lane & 3);
            float* dst;
            int ccol = col;
            if (C1 && col >= halfN) { dst = C1; ccol = col - halfN; }
            else                    { dst = C0; }
            *(float2*)(dst + (size_t)row * halfN + ccol) =
                make_float2(acc[mi][ni][0], acc[mi][ni][1]);
            *(float2*)(dst + (size_t)(row + 8) * halfN + ccol) =
                make_float2(acc[mi][ni][2], acc[mi][ni][3]);
        }
    }
}

// ---------------------------------------------------------------------------
// LayerNorm over last dim (64) per head.  One warp per 64-element row.
// ---------------------------------------------------------------------------
__global__ __launch_bounds__(256) void ln64(
    float* __restrict__ v, const float* __restrict__ gamma,
    const float* __restrict__ beta)
{
    int lane = threadIdx.x & 31;
    size_t row = (size_t)blockIdx.x * (blockDim.x >> 5) + (threadIdx.x >> 5);
    float* p = v + row * HDIM;
    float x0 = p[lane], x1 = p[lane + 32];
    float s  = x0 + x1;
    float ss = x0 * x0 + x1 * x1;
    #pragma unroll
    for (int o = 16; o > 0; o >>= 1) {
        s  += __shfl_xor_sync(0xffffffffu, s,  o);
        ss += __shfl_xor_sync(0xffffffffu, ss, o);
    }
    float mu  = s * (1.0f / HDIM);
    float var = ss * (1.0f / HDIM) - mu * mu;
    float r   = rsqrtf(var + 1e-5f);
    p[lane]      = (x0 - mu) * r * gamma[lane]      + beta[lane];
    p[lane + 32] = (x1 - mu) * r * gamma[lane + 32] + beta[lane + 32];
}

// ---------------------------------------------------------------------------
// Tensor-core flash sigmoid attention (tf32 mma).
// CTA: 128 q-rows of one (b,h).  8 warps, warp w owns rows w*16..w*16+15.
// kv tiles of 64; causal tile limit jmax = 2*qb+1.
// Smem (dynamic, 70656 B):
//   sP [128][68] : Q staging, then P (per-warp private rows)
//   sK [64][68]  : K tile, row-major [kv][d]
//   sV [64][72]  : V tile, row-major [kv][d]
// Pads chosen so all fragment LDS patterns are bank-conflict-free.
// ---------------------------------------------------------------------------
__global__ __launch_bounds__(256) void attn_tc(
    const float* __restrict__ qh, const float* __restrict__ kb,
    const float* __restrict__ vb, float* __restrict__ out)
{
    extern __shared__ float sm[];
    float* sP = sm;                         // 128*68 = 8704 floats
    float* sK = sm + 128 * 68;              // 64*68  = 4352
    float* sV = sK + 64 * 68;               // 64*72  = 4608

    const int t = threadIdx.x, lane = t & 31, warp = t >> 5;
    const int qb = blockIdx.x, h = blockIdx.y, b = blockIdx.z;
    const int q0 = qb * 128;

    const float* Qb = qh + ((size_t)(b * SQL + q0)) * DMODEL + h * HDIM;
    const float* Kb = kb + ((size_t)b * SQL) * DMODEL + h * HDIM;
    const float* Vb = vb + ((size_t)b * SQL) * DMODEL + h * HDIM;

    // stage Q (tf32) into sP: thread t -> row t>>1, cols (t&1)*32 .. +31
    {
        int r = t >> 1, c0 = (t & 1) * 32;
        const float* src = Qb + (size_t)r * DMODEL + c0;
        #pragma unroll
        for (int i = 0; i < 8; i++) {
            float4 v4 = *(const float4*)(src + i * 4);
            float* d = &sP[r * 68 + c0 + i * 4];
            d[0] = f2tf32(v4.x); d[1] = f2tf32(v4.y);
            d[2] = f2tf32(v4.z); d[3] = f2tf32(v4.w);
        }
    }
    __syncthreads();

    // persistent Q A-fragments (16 rows x 64 k) in registers
    unsigned qf[8][4];
    {
        int r = warp * 16 + (lane >> 2);
        #pragma unroll
        for (int kk = 0; kk < 8; kk++) {
            int c = kk * 8 + (lane & 3);
            qf[kk][0] = __float_as_uint(sP[r * 68 + c]);
            qf[kk][1] = __float_as_uint(sP[(r + 8) * 68 + c]);
            qf[kk][2] = __float_as_uint(sP[r * 68 + c + 4]);
            qf[kk][3] = __float_as_uint(sP[(r + 8) * 68 + c + 4]);
        }
    }

    float oacc[8][4];
    #pragma unroll
    for (int ni = 0; ni < 8; ni++)
        #pragma unroll
        for (int r = 0; r < 4; r++) oacc[ni][r] = 0.0f;

    const int jmax = 2 * qb + 1;
    const int sr = t >> 2, sc = (t & 3) * 16;    // K/V staging map

    // prefetch tile 0
    float4 kreg[4], vreg[4];
    {
        const float* ks = Kb + (size_t)sr * DMODEL + sc;
        const float* vs = Vb + (size_t)sr * DMODEL + sc;
        #pragma unroll
        for (int i = 0; i < 4; i++) {
            kreg[i] = *(const float4*)(ks + i * 4);
            vreg[i] = *(const float4*)(vs + i * 4);
        }
    }

    for (int j = 0; j <= jmax; j++) {
        __syncthreads();   // prior S/PV reads of sK/sV complete
        #pragma unroll
        for (int i = 0; i < 4; i++) {
            float* dk = &sK[sr * 68 + sc + i * 4];
            dk[0] = f2tf32(kreg[i].x); dk[1] = f2tf32(kreg[i].y);
            dk[2] = f2tf32(kreg[i].z); dk[3] = f2tf32(kreg[i].w);
            float* dv = &sV[sr * 72 + sc + i * 4];
            dv[0] = f2tf32(vreg[i].x); dv[1] = f2tf32(vreg[i].y);
            dv[2] = f2tf32(vreg[i].z); dv[3] = f2tf32(vreg[i].w);
        }
        __syncthreads();
        // prefetch next tile (overlaps with math below)
        if (j < jmax) {
            const float* ks = Kb + (size_t)((j + 1) * 64 + sr) * DMODEL + sc;
            const float* vs = Vb + (size_t)((j + 1) * 64 + sr) * DMODEL + sc;
            #pragma unroll
            for (int i = 0; i < 4; i++) {
                kreg[i] = *(const float4*)(ks + i * 4);
                vreg[i] = *(const float4*)(vs + i * 4);
            }
        }

        // S = Q K^T   (B[k=d][n=kv] = sK[kv][d], read sK[cb][kr])
        float sfr[8][4];
        #pragma unroll
        for (int ni = 0; ni < 8; ni++)
            #pragma unroll
            for (int r = 0; r < 4; r++) sfr[ni][r] = 0.0f;
        #pragma unroll
        for (int kk = 0; kk < 8; kk++) {
            #pragma unroll
            for (int ni = 0; ni < 8; ni++) {
                int cb = ni * 8 + (lane >> 2);
                int kr = kk * 8 + (lane & 3);
                unsigned bbf[2];
                bbf[0] = __float_as_uint(sK[cb * 68 + kr]);
                bbf[1] = __float_as_uint(sK[cb * 68 + kr + 4]);
                mma_tf32(sfr[ni], qf[kk], bbf);
            }
        }

        // sigmoid + causal mask -> P in sP (per-warp rows)
        {
            int r = warp * 16 + (lane >> 2);
            int g0 = q0 + r, g1 = g0 + 8;
            #pragma unroll
            for (int ni = 0; ni < 8; ni++) {
                int c  = ni * 8 + 2 * (lane & 3);
                int gc = j * 64 + c;
                float p00 = __fdividef(1.f, 1.f + __expf(8.f - sfr[ni][0] * 0.125f));
                float p01 = __fdividef(1.f, 1.f + __expf(8.f - sfr[ni][1] * 0.125f));
                float p10 = __fdividef(1.f, 1.f + __expf(8.f - sfr[ni][2] * 0.125f));
                float p11 = __fdividef(1.f, 1.f + __expf(8.f - sfr[ni][3] * 0.125f));
                p00 = (gc     <= g0) ? p00 : 0.f;
                p01 = (gc + 1 <= g0) ? p01 : 0.f;
                p10 = (gc     <= g1) ? p10 : 0.f;
                p11 = (gc + 1 <= g1) ? p11 : 0.f;
                sP[r * 68 + c]           = f2tf32(p00);
                sP[r * 68 + c + 1]       = f2tf32(p01);
                sP[(r + 8) * 68 + c]     = f2tf32(p10);
                sP[(r + 8) * 68 + c + 1] = f2tf32(p11);
            }
        }
        __syncwarp();   // sP rows are warp-private

        // O += P V   (B[k=kv][n=d] = sV[kv][d], read sV[kr][cb])
        #pragma unroll
        for (int kk = 0; kk < 8; kk++) {
            int r = warp * 16 + (lane >> 2);
            int c = kk * 8 + (lane & 3);
            unsigned pf[4];
            pf[0] = __float_as_uint(sP[r * 68 + c]);
            pf[1] = __float_as_uint(sP[(r + 8) * 68 + c]);
            pf[2] = __float_as_uint(sP[r * 68 + c + 4]);
            pf[3] = __float_as_uint(sP[(r + 8) * 68 + c + 4]);
            #pragma unroll
            for (int ni = 0; ni < 8; ni++) {
                int cb = ni * 8 + (lane >> 2);
                int kr = kk * 8 + (lane & 3);
                unsigned bbf[2];
                bbf[0] = __float_as_uint(sV[kr * 72 + cb]);
                bbf[1] = __float_as_uint(sV[(kr + 4) * 72 + cb]);
                mma_tf32(oacc[ni], pf, bbf);
            }
        }
    }

    // epilogue
    {
        int r = warp * 16 + (lane >> 2);
        float* ob = out + ((size_t)(b * SQL + q0 + r)) * DMODEL + h * HDIM;
        #pragma unroll
        for (int ni = 0; ni < 8; ni++) {
            int c = ni * 8 + 2 * (lane & 3);
            *(float2*)(ob + c) = make_float2(oacc[ni][0], oacc[ni][1]);
            *(float2*)(ob + (size_t)8 * DMODEL + c) =
                make_float2(oacc[ni][2], oacc[ni][3]);
        }
    }
}

#define ATTN_SMEM ((128 * 68 + 64 * 68 + 64 * 72) * 4)   // 70656 B

// ---------------------------------------------------------------------------
extern "C" void kernel_launch(void* const* d_in, const int* in_sizes, int n_in,
                              void* d_out, int out_size)
{
    const float* q     = (const float*)d_in[0];
    const float* kv    = (const float*)d_in[1];
    const float* Wq    = (const float*)d_in[2];
    const float* Wkv   = (const float*)d_in[3];
    const float* gamma = (const float*)d_in[4];
    const float* beta  = (const float*)d_in[5];
    const float* Wproj = (const float*)d_in[6];
    float* out = (float*)d_out;

    float *qh, *kbuf, *vbuf;
    cudaGetSymbolAddress((void**)&qh,   g_qh);
    cudaGetSymbolAddress((void**)&kbuf, g_k);
    cudaGetSymbolAddress((void**)&vbuf, g_v);

    cudaFuncSetAttribute(attn_tc,
        cudaFuncAttributeMaxDynamicSharedMemorySize, ATTN_SMEM);

    const int M = NB * SQL;   // 4096

    // 1) qh = q @ Wq
    gemm_tc<<<dim3(DMODEL / 128, M / 128), 256>>>(
        q, Wq, qh, nullptr, M, DMODEL, DMODEL, DMODEL);

    // 2) kvh = kv @ Wkv, split into K (cols < 1024) and V (cols >= 1024)
    gemm_tc<<<dim3(2 * DMODEL / 128, M / 128), 256>>>(
        kv, Wkv, kbuf, vbuf, M, 2 * DMODEL, DMODEL, DMODEL);

    // 3) per-head LayerNorm of V
    ln64<<<(NB * SQL * NH) / 8, 256>>>(vbuf, gamma, beta);

    // 4) attention -> attn_times_v (first half of d_out)
    attn_tc<<<dim3(SQL / 128, NH, NB), 256, ATTN_SMEM>>>(qh, kbuf, vbuf, out);

    // 5) attn_proj = attn_times_v @ Wproj (second half of d_out)
    gemm_tc<<<dim3(DMODEL / 128, M / 128), 256>>>(
        out, Wproj, out + (size_t)M * DMODEL, nullptr, M, DMODEL, DMODEL, DMODEL);
}

// round 5
// speedup vs baseline: 2.8221x; 1.0520x over previous
#include <cuda_runtime.h>
#include <cuda_bf16.h>

#define SQL 2048
#define DMODEL 1024
#define NB 2
#define NH 16
#define HDIM 64

// Scratch (allocation-free rule: __device__ globals)
__device__ float g_qh[(size_t)NB * SQL * DMODEL];
__device__ float g_k [(size_t)NB * SQL * DMODEL];
__device__ float g_v [(size_t)NB * SQL * DMODEL];

// ---------------------------------------------------------------------------
// tf32 helpers
// ---------------------------------------------------------------------------
__device__ __forceinline__ float f2tf32(float x) {
    unsigned u;
    asm("cvt.rna.tf32.f32 %0, %1;" : "=r"(u) : "f"(x));
    return __uint_as_float(u);
}

__device__ __forceinline__ void mma_tf32(
    float* c, const unsigned* a, const unsigned* b)
{
    asm volatile(
        "mma.sync.aligned.m16n8k8.row.col.f32.tf32.tf32.f32 "
        "{%0,%1,%2,%3}, {%4,%5,%6,%7}, {%8,%9}, {%0,%1,%2,%3};"
        : "+f"(c[0]), "+f"(c[1]), "+f"(c[2]), "+f"(c[3])
        : "r"(a[0]), "r"(a[1]), "r"(a[2]), "r"(a[3]),
          "r"(b[0]), "r"(b[1]));
}

// ---------------------------------------------------------------------------
// tf32 tensor-core GEMM, 128x128x16 tile, 8 warps (64x32 warp-tile each),
// DOUBLE-BUFFERED smem: one barrier per k-iter; math on buf overlaps the
// global load + store of buf^1.
// C = A[M,K] @ B[K,N].  If C1 != nullptr, cols >= halfN go to C1 (width
// halfN), cols < halfN go to C0 (width halfN).
// ---------------------------------------------------------------------------
__global__ __launch_bounds__(256) void gemm_tc(
    const float* __restrict__ A, const float* __restrict__ Bm,
    float* __restrict__ C0, float* __restrict__ C1,
    int M, int N, int K, int halfN)
{
    __shared__ float sA[2][128][20];    // [buf][row][k]  (pad 16 -> 20)
    __shared__ float sB[2][16][136];    // [buf][k][col]  (pad 128 -> 136)

    int t    = threadIdx.x;
    int lane = t & 31;
    int warp = t >> 5;
    int wm   = warp >> 2;
    int wn   = warp & 3;
    int brow = blockIdx.y * 128, bcol = blockIdx.x * 128;

    float acc[4][4][4];
    #pragma unroll
    for (int mi = 0; mi < 4; mi++)
        #pragma unroll
        for (int ni = 0; ni < 4; ni++)
            #pragma unroll
            for (int r = 0; r < 4; r++) acc[mi][ni][r] = 0.0f;

    const float* Ap0 = A + (size_t)(brow + (t >> 2)) * K + (t & 3) * 4;
    const float* Ap1 = Ap0 + (size_t)64 * K;
    const float* Bp0 = Bm + (size_t)(t >> 5) * N + bcol + (t & 31) * 4;
    const float* Bp1 = Bp0 + (size_t)8 * N;

    int arow = t >> 2,  acg = (t & 3) * 4;
    int bk   = t >> 5,  bcg = (t & 31) * 4;

    float4 a40 = *(const float4*)(Ap0);
    float4 a41 = *(const float4*)(Ap1);
    float4 b40 = *(const float4*)(Bp0);
    float4 b41 = *(const float4*)(Bp1);

    // stage tile 0 into buf 0
    {
        float4 v;
        v = make_float4(f2tf32(a40.x), f2tf32(a40.y), f2tf32(a40.z), f2tf32(a40.w));
        *(float4*)&sA[0][arow][acg] = v;
        v = make_float4(f2tf32(a41.x), f2tf32(a41.y), f2tf32(a41.z), f2tf32(a41.w));
        *(float4*)&sA[0][arow + 64][acg] = v;
        v = make_float4(f2tf32(b40.x), f2tf32(b40.y), f2tf32(b40.z), f2tf32(b40.w));
        *(float4*)&sB[0][bk][bcg] = v;
        v = make_float4(f2tf32(b41.x), f2tf32(b41.y), f2tf32(b41.z), f2tf32(b41.w));
        *(float4*)&sB[0][bk + 8][bcg] = v;
    }
    __syncthreads();

    int buf = 0;
    for (int k0 = 0; k0 < K; k0 += 16, buf ^= 1) {
        bool has_next = (k0 + 16) < K;
        if (has_next) {
            a40 = *(const float4*)(Ap0 + (k0 + 16));
            a41 = *(const float4*)(Ap1 + (k0 + 16));
            b40 = *(const float4*)(Bp0 + (size_t)(k0 + 16) * N);
            b41 = *(const float4*)(Bp1 + (size_t)(k0 + 16) * N);
        }
        // math on buf (LDG latency above hidden by this)
        #pragma unroll
        for (int ks = 0; ks < 16; ks += 8) {
            unsigned af[4][4];
            #pragma unroll
            for (int mi = 0; mi < 4; mi++) {
                int r = wm * 64 + mi * 16 + (lane >> 2);
                int c = ks + (lane & 3);
                af[mi][0] = __float_as_uint(sA[buf][r][c]);
                af[mi][1] = __float_as_uint(sA[buf][r + 8][c]);
                af[mi][2] = __float_as_uint(sA[buf][r][c + 4]);
                af[mi][3] = __float_as_uint(sA[buf][r + 8][c + 4]);
            }
            unsigned bf[4][2];
            #pragma unroll
            for (int ni = 0; ni < 4; ni++) {
                int cb = wn * 32 + ni * 8 + (lane >> 2);
                int kr = ks + (lane & 3);
                bf[ni][0] = __float_as_uint(sB[buf][kr][cb]);
                bf[ni][1] = __float_as_uint(sB[buf][kr + 4][cb]);
            }
            #pragma unroll
            for (int mi = 0; mi < 4; mi++)
                #pragma unroll
                for (int ni = 0; ni < 4; ni++)
                    mma_tf32(acc[mi][ni], af[mi], bf[ni]);
        }
        // stage next tile into buf^1 (no reader until after the barrier)
        if (has_next) {
            int nb = buf ^ 1;
            float4 v;
            v = make_float4(f2tf32(a40.x), f2tf32(a40.y), f2tf32(a40.z), f2tf32(a40.w));
            *(float4*)&sA[nb][arow][acg] = v;
            v = make_float4(f2tf32(a41.x), f2tf32(a41.y), f2tf32(a41.z), f2tf32(a41.w));
            *(float4*)&sA[nb][arow + 64][acg] = v;
            v = make_float4(f2tf32(b40.x), f2tf32(b40.y), f2tf32(b40.z), f2tf32(b40.w));
            *(float4*)&sB[nb][bk][bcg] = v;
            v = make_float4(f2tf32(b41.x), f2tf32(b41.y), f2tf32(b41.z), f2tf32(b41.w));
            *(float4*)&sB[nb][bk + 8][bcg] = v;
        }
        __syncthreads();
    }

    #pragma unroll
    for (int mi = 0; mi < 4; mi++) {
        #pragma unroll
        for (int ni = 0; ni < 4; ni++) {
            int row = brow + wm * 64 + mi * 16 + (lane >> 2);
            int col = bcol + wn * 32 + ni * 8 + 2 * (lane & 3);
            float* dst;
            int ccol = col;
            if (C1 && col >= halfN) { dst = C1; ccol = col - halfN; }
            else                    { dst = C0; }
            *(float2*)(dst + (size_t)row * halfN + ccol) =
                make_float2(acc[mi][ni][0], acc[mi][ni][1]);
            *(float2*)(dst + (size_t)(row + 8) * halfN + ccol) =
                make_float2(acc[mi][ni][2], acc[mi][ni][3]);
        }
    }
}

// ---------------------------------------------------------------------------
// LayerNorm over last dim (64) per head.  One warp per 64-element row.
// ---------------------------------------------------------------------------
__global__ __launch_bounds__(256) void ln64(
    float* __restrict__ v, const float* __restrict__ gamma,
    const float* __restrict__ beta)
{
    int lane = threadIdx.x & 31;
    size_t row = (size_t)blockIdx.x * (blockDim.x >> 5) + (threadIdx.x >> 5);
    float* p = v + row * HDIM;
    float x0 = p[lane], x1 = p[lane + 32];
    float s  = x0 + x1;
    float ss = x0 * x0 + x1 * x1;
    #pragma unroll
    for (int o = 16; o > 0; o >>= 1) {
        s  += __shfl_xor_sync(0xffffffffu, s,  o);
        ss += __shfl_xor_sync(0xffffffffu, ss, o);
    }
    float mu  = s * (1.0f / HDIM);
    float var = ss * (1.0f / HDIM) - mu * mu;
    float r   = rsqrtf(var + 1e-5f);
    p[lane]      = (x0 - mu) * r * gamma[lane]      + beta[lane];
    p[lane + 32] = (x1 - mu) * r * gamma[lane + 32] + beta[lane + 32];
}

// ---------------------------------------------------------------------------
// Tensor-core flash sigmoid attention v2 (tf32 mma), 2D warp split.
// CTA: 128 q-rows of one (b,h).  8 warps = (wm in 0..3) x (wn in 0..1).
// Warp (wm,wn) owns m-tiles {2wm, 2wm+1} (32 rows) and the 32-wide
// n-half wn for S, d-half wn for O.  K/V B-fragments are read once per
// warp and reused across both m-tiles; P goes through shared sP with a
// cross-warp __syncthreads.
// Smem (dynamic, 105472 B):
//   sQ [128][68] : Q (tf32), persistent
//   sP [128][68] : P tile (tf32), rewritten per kv-tile
//   sK [64][68]  : K tile [kv][d]
//   sV [64][72]  : V tile [kv][d]
// All fragment-read patterns bank-conflict-free (4a+b / 8b+a forms).
// ---------------------------------------------------------------------------
__global__ __launch_bounds__(256) void attn_tc(
    const float* __restrict__ qh, const float* __restrict__ kb,
    const float* __restrict__ vb, float* __restrict__ out)
{
    extern __shared__ float sm[];
    float* sQ = sm;                          // 128*68 = 8704
    float* sP = sQ + 128 * 68;               // 8704
    float* sK = sP + 128 * 68;               // 64*68 = 4352
    float* sV = sK + 64 * 68;                // 64*72 = 4608

    const int t = threadIdx.x, lane = t & 31, warp = t >> 5;
    const int wm = warp >> 1, wn = warp & 1;
    const int qb = blockIdx.x, h = blockIdx.y, b = blockIdx.z;
    const int q0 = qb * 128;

    const float* Qb = qh + ((size_t)(b * SQL + q0)) * DMODEL + h * HDIM;
    const float* Kb = kb + ((size_t)b * SQL) * DMODEL + h * HDIM;
    const float* Vb = vb + ((size_t)b * SQL) * DMODEL + h * HDIM;

    // stage Q (tf32) into sQ: thread t -> row t>>1, cols (t&1)*32 .. +31
    {
        int r = t >> 1, c0 = (t & 1) * 32;
        const float* src = Qb + (size_t)r * DMODEL + c0;
        #pragma unroll
        for (int i = 0; i < 8; i++) {
            float4 v4 = *(const float4*)(src + i * 4);
            float* d = &sQ[r * 68 + c0 + i * 4];
            d[0] = f2tf32(v4.x); d[1] = f2tf32(v4.y);
            d[2] = f2tf32(v4.z); d[3] = f2tf32(v4.w);
        }
    }
    __syncthreads();

    // persistent Q A-fragments for both m-tiles
    unsigned qf[2][8][4];
    #pragma unroll
    for (int mt = 0; mt < 2; mt++) {
        int r = (2 * wm + mt) * 16 + (lane >> 2);
        #pragma unroll
        for (int kk = 0; kk < 8; kk++) {
            int c = kk * 8 + (lane & 3);
            qf[mt][kk][0] = __float_as_uint(sQ[r * 68 + c]);
            qf[mt][kk][1] = __float_as_uint(sQ[(r + 8) * 68 + c]);
            qf[mt][kk][2] = __float_as_uint(sQ[r * 68 + c + 4]);
            qf[mt][kk][3] = __float_as_uint(sQ[(r + 8) * 68 + c + 4]);
        }
    }

    float oacc[2][4][4];
    #pragma unroll
    for (int mt = 0; mt < 2; mt++)
        #pragma unroll
        for (int ni = 0; ni < 4; ni++)
            #pragma unroll
            for (int r = 0; r < 4; r++) oacc[mt][ni][r] = 0.0f;

    const int jmax = 2 * qb + 1;
    const int sr = t >> 2, sc = (t & 3) * 16;    // K/V staging map

    // prefetch tile 0
    float4 kreg[4], vreg[4];
    {
        const float* ks = Kb + (size_t)sr * DMODEL + sc;
        const float* vs = Vb + (size_t)sr * DMODEL + sc;
        #pragma unroll
        for (int i = 0; i < 4; i++) {
            kreg[i] = *(const float4*)(ks + i * 4);
            vreg[i] = *(const float4*)(vs + i * 4);
        }
    }

    for (int j = 0; j <= jmax; j++) {
        __syncthreads();   // prior tile's reads of sK/sV/sP complete
        #pragma unroll
        for (int i = 0; i < 4; i++) {
            float* dk = &sK[sr * 68 + sc + i * 4];
            dk[0] = f2tf32(kreg[i].x); dk[1] = f2tf32(kreg[i].y);
            dk[2] = f2tf32(kreg[i].z); dk[3] = f2tf32(kreg[i].w);
            float* dv = &sV[sr * 72 + sc + i * 4];
            dv[0] = f2tf32(vreg[i].x); dv[1] = f2tf32(vreg[i].y);
            dv[2] = f2tf32(vreg[i].z); dv[3] = f2tf32(vreg[i].w);
        }
        __syncthreads();
        // prefetch next tile (overlaps with math below)
        if (j < jmax) {
            const float* ks = Kb + (size_t)((j + 1) * 64 + sr) * DMODEL + sc;
            const float* vs = Vb + (size_t)((j + 1) * 64 + sr) * DMODEL + sc;
            #pragma unroll
            for (int i = 0; i < 4; i++) {
                kreg[i] = *(const float4*)(ks + i * 4);
                vreg[i] = *(const float4*)(vs + i * 4);
            }
        }

        // S = Q K^T on this warp's n-half; B-frags shared across m-tiles
        float sfr[2][4][4];
        #pragma unroll
        for (int mt = 0; mt < 2; mt++)
            #pragma unroll
            for (int ni = 0; ni < 4; ni++)
                #pragma unroll
                for (int r = 0; r < 4; r++) sfr[mt][ni][r] = 0.0f;
        #pragma unroll
        for (int kk = 0; kk < 8; kk++) {
            #pragma unroll
            for (int ni = 0; ni < 4; ni++) {
                int cb = wn * 32 + ni * 8 + (lane >> 2);
                int kr = kk * 8 + (lane & 3);
                unsigned bbf[2];
                bbf[0] = __float_as_uint(sK[cb * 68 + kr]);
                bbf[1] = __float_as_uint(sK[cb * 68 + kr + 4]);
                mma_tf32(sfr[0][ni], qf[0][kk], bbf);
                mma_tf32(sfr[1][ni], qf[1][kk], bbf);
            }
        }

        // sigmoid + causal mask -> P into shared sP
        #pragma unroll
        for (int mt = 0; mt < 2; mt++) {
            int r = (2 * wm + mt) * 16 + (lane >> 2);
            int g0 = q0 + r, g1 = g0 + 8;
            #pragma unroll
            for (int ni = 0; ni < 4; ni++) {
                int c  = wn * 32 + ni * 8 + 2 * (lane & 3);
                int gc = j * 64 + c;
                float p00 = __fdividef(1.f, 1.f + __expf(8.f - sfr[mt][ni][0] * 0.125f));
                float p01 = __fdividef(1.f, 1.f + __expf(8.f - sfr[mt][ni][1] * 0.125f));
                float p10 = __fdividef(1.f, 1.f + __expf(8.f - sfr[mt][ni][2] * 0.125f));
                float p11 = __fdividef(1.f, 1.f + __expf(8.f - sfr[mt][ni][3] * 0.125f));
                p00 = (gc     <= g0) ? p00 : 0.f;
                p01 = (gc + 1 <= g0) ? p01 : 0.f;
                p10 = (gc     <= g1) ? p10 : 0.f;
                p11 = (gc + 1 <= g1) ? p11 : 0.f;
                sP[r * 68 + c]           = f2tf32(p00);
                sP[r * 68 + c + 1]       = f2tf32(p01);
                sP[(r + 8) * 68 + c]     = f2tf32(p10);
                sP[(r + 8) * 68 + c + 1] = f2tf32(p11);
            }
        }
        __syncthreads();   // full P tile visible across warps

        // O += P V on this warp's d-half; V B-frags shared across m-tiles
        #pragma unroll
        for (int kk = 0; kk < 8; kk++) {
            unsigned pf[2][4];
            #pragma unroll
            for (int mt = 0; mt < 2; mt++) {
                int r = (2 * wm + mt) * 16 + (lane >> 2);
                int c = kk * 8 + (lane & 3);
                pf[mt][0] = __float_as_uint(sP[r * 68 + c]);
                pf[mt][1] = __float_as_uint(sP[(r + 8) * 68 + c]);
                pf[mt][2] = __float_as_uint(sP[r * 68 + c + 4]);
                pf[mt][3] = __float_as_uint(sP[(r + 8) * 68 + c + 4]);
            }
            #pragma unroll
            for (int ni = 0; ni < 4; ni++) {
                int cb = wn * 32 + ni * 8 + (lane >> 2);
                int kr = kk * 8 + (lane & 3);
                unsigned bbf[2];
                bbf[0] = __float_as_uint(sV[kr * 72 + cb]);
                bbf[1] = __float_as_uint(sV[(kr + 4) * 72 + cb]);
                mma_tf32(oacc[0][ni], pf[0], bbf);
                mma_tf32(oacc[1][ni], pf[1], bbf);
            }
        }
    }

    // epilogue
    #pragma unroll
    for (int mt = 0; mt < 2; mt++) {
        int r = (2 * wm + mt) * 16 + (lane >> 2);
        float* ob = out + ((size_t)(b * SQL + q0 + r)) * DMODEL + h * HDIM;
        #pragma unroll
        for (int ni = 0; ni < 4; ni++) {
            int c = wn * 32 + ni * 8 + 2 * (lane & 3);
            *(float2*)(ob + c) = make_float2(oacc[mt][ni][0], oacc[mt][ni][1]);
            *(float2*)(ob + (size_t)8 * DMODEL + c) =
                make_float2(oacc[mt][ni][2], oacc[mt][ni][3]);
        }
    }
}

#define ATTN_SMEM ((128 * 68 * 2 + 64 * 68 + 64 * 72) * 4)   // 105472 B

// ---------------------------------------------------------------------------
extern "C" void kernel_launch(void* const* d_in, const int* in_sizes, int n_in,
                              void* d_out, int out_size)
{
    const float* q     = (const float*)d_in[0];
    const float* kv    = (const float*)d_in[1];
    const float* Wq    = (const float*)d_in[2];
    const float* Wkv   = (const float*)d_in[3];
    const float* gamma = (const float*)d_in[4];
    const float* beta  = (const float*)d_in[5];
    const float* Wproj = (const float*)d_in[6];
    float* out = (float*)d_out;

    float *qh, *kbuf, *vbuf;
    cudaGetSymbolAddress((void**)&qh,   g_qh);
    cudaGetSymbolAddress((void**)&kbuf, g_k);
    cudaGetSymbolAddress((void**)&vbuf, g_v);

    cudaFuncSetAttribute(attn_tc,
        cudaFuncAttributeMaxDynamicSharedMemorySize, ATTN_SMEM);

    const int M = NB * SQL;   // 4096

    // 1) qh = q @ Wq
    gemm_tc<<<dim3(DMODEL / 128, M / 128), 256>>>(
        q, Wq, qh, nullptr, M, DMODEL, DMODEL, DMODEL);

    // 2) kvh = kv @ Wkv, split into K (cols < 1024) and V (cols >= 1024)
    gemm_tc<<<dim3(2 * DMODEL / 128, M / 128), 256>>>(
        kv, Wkv, kbuf, vbuf, M, 2 * DMODEL, DMODEL, DMODEL);

    // 3) per-head LayerNorm of V
    ln64<<<(NB * SQL * NH) / 8, 256>>>(vbuf, gamma, beta);

    // 4) attention -> attn_times_v (first half of d_out)
    attn_tc<<<dim3(SQL / 128, NH, NB), 256, ATTN_SMEM>>>(qh, kbuf, vbuf, out);

    // 5) attn_proj = attn_times_v @ Wproj (second half of d_out)
    gemm_tc<<<dim3(DMODEL / 128, M / 128), 256>>>(
        out, Wproj, out + (size_t)M * DMODEL, nullptr, M, DMODEL, DMODEL, DMODEL);
}

// round 6
// speedup vs baseline: 2.9037x; 1.0289x over previous
#include <cuda_runtime.h>
#include <cuda_bf16.h>

#define SQL 2048
#define DMODEL 1024
#define NB 2
#define NH 16
#define HDIM 64

// Scratch (allocation-free rule: __device__ globals)
__device__ float g_qh[(size_t)NB * SQL * DMODEL];
__device__ float g_k [(size_t)NB * SQL * DMODEL];
__device__ float g_v [(size_t)NB * SQL * DMODEL];

// ---------------------------------------------------------------------------
// tf32 / cp.async helpers
// ---------------------------------------------------------------------------
__device__ __forceinline__ float f2tf32(float x) {
    unsigned u;
    asm("cvt.rna.tf32.f32 %0, %1;" : "=r"(u) : "f"(x));
    return __uint_as_float(u);
}

__device__ __forceinline__ void mma_tf32(
    float* c, const unsigned* a, const unsigned* b)
{
    asm volatile(
        "mma.sync.aligned.m16n8k8.row.col.f32.tf32.tf32.f32 "
        "{%0,%1,%2,%3}, {%4,%5,%6,%7}, {%8,%9}, {%0,%1,%2,%3};"
        : "+f"(c[0]), "+f"(c[1]), "+f"(c[2]), "+f"(c[3])
        : "r"(a[0]), "r"(a[1]), "r"(a[2]), "r"(a[3]),
          "r"(b[0]), "r"(b[1]));
}

__device__ __forceinline__ void cp16(unsigned smem_dst, const void* gsrc) {
    asm volatile("cp.async.cg.shared.global [%0], [%1], 16;\n"
                 :: "r"(smem_dst), "l"(gsrc));
}
#define CP_COMMIT() asm volatile("cp.async.commit_group;\n" ::: "memory")
#define CP_WAIT(n)  asm volatile("cp.async.wait_group %0;\n" :: "n"(n) : "memory")

// ---------------------------------------------------------------------------
// tf32 tensor-core GEMM, 128x128x16 tile, 8 warps (64x32 warp-tile each),
// double-buffered smem.  C = A[M,K] @ B[K,N].  If C1 != nullptr, cols >=
// halfN go to C1 (width halfN), else C0.  do_cvt: round outputs to tf32
// (for buffers that feed later tf32 mma stages).
// ---------------------------------------------------------------------------
__global__ __launch_bounds__(256) void gemm_tc(
    const float* __restrict__ A, const float* __restrict__ Bm,
    float* __restrict__ C0, float* __restrict__ C1,
    int M, int N, int K, int halfN, int do_cvt)
{
    __shared__ float sA[2][128][20];
    __shared__ float sB[2][16][136];

    int t    = threadIdx.x;
    int lane = t & 31;
    int warp = t >> 5;
    int wm   = warp >> 2;
    int wn   = warp & 3;
    int brow = blockIdx.y * 128, bcol = blockIdx.x * 128;

    float acc[4][4][4];
    #pragma unroll
    for (int mi = 0; mi < 4; mi++)
        #pragma unroll
        for (int ni = 0; ni < 4; ni++)
            #pragma unroll
            for (int r = 0; r < 4; r++) acc[mi][ni][r] = 0.0f;

    const float* Ap0 = A + (size_t)(brow + (t >> 2)) * K + (t & 3) * 4;
    const float* Ap1 = Ap0 + (size_t)64 * K;
    const float* Bp0 = Bm + (size_t)(t >> 5) * N + bcol + (t & 31) * 4;
    const float* Bp1 = Bp0 + (size_t)8 * N;

    int arow = t >> 2,  acg = (t & 3) * 4;
    int bk   = t >> 5,  bcg = (t & 31) * 4;

    float4 a40 = *(const float4*)(Ap0);
    float4 a41 = *(const float4*)(Ap1);
    float4 b40 = *(const float4*)(Bp0);
    float4 b41 = *(const float4*)(Bp1);

    {
        float4 v;
        v = make_float4(f2tf32(a40.x), f2tf32(a40.y), f2tf32(a40.z), f2tf32(a40.w));
        *(float4*)&sA[0][arow][acg] = v;
        v = make_float4(f2tf32(a41.x), f2tf32(a41.y), f2tf32(a41.z), f2tf32(a41.w));
        *(float4*)&sA[0][arow + 64][acg] = v;
        v = make_float4(f2tf32(b40.x), f2tf32(b40.y), f2tf32(b40.z), f2tf32(b40.w));
        *(float4*)&sB[0][bk][bcg] = v;
        v = make_float4(f2tf32(b41.x), f2tf32(b41.y), f2tf32(b41.z), f2tf32(b41.w));
        *(float4*)&sB[0][bk + 8][bcg] = v;
    }
    __syncthreads();

    int buf = 0;
    for (int k0 = 0; k0 < K; k0 += 16, buf ^= 1) {
        bool has_next = (k0 + 16) < K;
        if (has_next) {
            a40 = *(const float4*)(Ap0 + (k0 + 16));
            a41 = *(const float4*)(Ap1 + (k0 + 16));
            b40 = *(const float4*)(Bp0 + (size_t)(k0 + 16) * N);
            b41 = *(const float4*)(Bp1 + (size_t)(k0 + 16) * N);
        }
        #pragma unroll
        for (int ks = 0; ks < 16; ks += 8) {
            unsigned af[4][4];
            #pragma unroll
            for (int mi = 0; mi < 4; mi++) {
                int r = wm * 64 + mi * 16 + (lane >> 2);
                int c = ks + (lane & 3);
                af[mi][0] = __float_as_uint(sA[buf][r][c]);
                af[mi][1] = __float_as_uint(sA[buf][r + 8][c]);
                af[mi][2] = __float_as_uint(sA[buf][r][c + 4]);
                af[mi][3] = __float_as_uint(sA[buf][r + 8][c + 4]);
            }
            unsigned bf[4][2];
            #pragma unroll
            for (int ni = 0; ni < 4; ni++) {
                int cb = wn * 32 + ni * 8 + (lane >> 2);
                int kr = ks + (lane & 3);
                bf[ni][0] = __float_as_uint(sB[buf][kr][cb]);
                bf[ni][1] = __float_as_uint(sB[buf][kr + 4][cb]);
            }
            #pragma unroll
            for (int mi = 0; mi < 4; mi++)
                #pragma unroll
                for (int ni = 0; ni < 4; ni++)
                    mma_tf32(acc[mi][ni], af[mi], bf[ni]);
        }
        if (has_next) {
            int nb = buf ^ 1;
            float4 v;
            v = make_float4(f2tf32(a40.x), f2tf32(a40.y), f2tf32(a40.z), f2tf32(a40.w));
            *(float4*)&sA[nb][arow][acg] = v;
            v = make_float4(f2tf32(a41.x), f2tf32(a41.y), f2tf32(a41.z), f2tf32(a41.w));
            *(float4*)&sA[nb][arow + 64][acg] = v;
            v = make_float4(f2tf32(b40.x), f2tf32(b40.y), f2tf32(b40.z), f2tf32(b40.w));
            *(float4*)&sB[nb][bk][bcg] = v;
            v = make_float4(f2tf32(b41.x), f2tf32(b41.y), f2tf32(b41.z), f2tf32(b41.w));
            *(float4*)&sB[nb][bk + 8][bcg] = v;
        }
        __syncthreads();
    }

    #pragma unroll
    for (int mi = 0; mi < 4; mi++) {
        #pragma unroll
        for (int ni = 0; ni < 4; ni++) {
            int row = brow + wm * 64 + mi * 16 + (lane >> 2);
            int col = bcol + wn * 32 + ni * 8 + 2 * (lane & 3);
            float* dst;
            int ccol = col;
            if (C1 && col >= halfN) { dst = C1; ccol = col - halfN; }
            else                    { dst = C0; }
            float v0 = acc[mi][ni][0], v1 = acc[mi][ni][1];
            float v2 = acc[mi][ni][2], v3 = acc[mi][ni][3];
            if (do_cvt) { v0 = f2tf32(v0); v1 = f2tf32(v1);
                          v2 = f2tf32(v2); v3 = f2tf32(v3); }
            *(float2*)(dst + (size_t)row * halfN + ccol) = make_float2(v0, v1);
            *(float2*)(dst + (size_t)(row + 8) * halfN + ccol) = make_float2(v2, v3);
        }
    }
}

// ---------------------------------------------------------------------------
// LayerNorm over last dim (64) per head.  One warp per row.  Output is
// rounded to tf32 (consumed only by the tf32 attention mma).
// ---------------------------------------------------------------------------
__global__ __launch_bounds__(256) void ln64(
    float* __restrict__ v, const float* __restrict__ gamma,
    const float* __restrict__ beta)
{
    int lane = threadIdx.x & 31;
    size_t row = (size_t)blockIdx.x * (blockDim.x >> 5) + (threadIdx.x >> 5);
    float* p = v + row * HDIM;
    float x0 = p[lane], x1 = p[lane + 32];
    float s  = x0 + x1;
    float ss = x0 * x0 + x1 * x1;
    #pragma unroll
    for (int o = 16; o > 0; o >>= 1) {
        s  += __shfl_xor_sync(0xffffffffu, s,  o);
        ss += __shfl_xor_sync(0xffffffffu, ss, o);
    }
    float mu  = s * (1.0f / HDIM);
    float var = ss * (1.0f / HDIM) - mu * mu;
    float r   = rsqrtf(var + 1e-5f);
    p[lane]      = f2tf32((x0 - mu) * r * gamma[lane]      + beta[lane]);
    p[lane + 32] = f2tf32((x1 - mu) * r * gamma[lane + 32] + beta[lane + 32]);
}

// ---------------------------------------------------------------------------
// Tensor-core flash sigmoid attention v3 (tf32 mma).
// 512 threads / 16 warps; warp (mw = warp>>1 in 0..7, h = warp&1).
// S-phase : warp computes S rows 16mw..+15, cols 32h..+31.
// PV-phase: warp computes O rows 16mw..+15, cols 32h..+31.
// Inputs qh/k/v are ALREADY tf32-rounded in gmem (producer kernels), so
// staging is raw cp.async (no cvt, no staging registers), double-buffered.
// Smem: sQ (aliased as sP after Q-frag load) + sK[2] + sV[2] = 104 KB.
// ---------------------------------------------------------------------------
__global__ __launch_bounds__(512) void attn_tc(
    const float* __restrict__ qh, const float* __restrict__ kb,
    const float* __restrict__ vb, float* __restrict__ out)
{
    extern __shared__ float sm[];
    float* sQP = sm;                               // 128*68 = 8704 floats
    float* sK  = sQP + 128 * 68;                   // 2 * 64*68
    float* sV  = sK + 2 * 64 * 68;                 // 2 * 64*72

    const int t = threadIdx.x, lane = t & 31, warp = t >> 5;
    const int mw = warp >> 1, h = warp & 1;
    const int qb = blockIdx.x, hd = blockIdx.y, b = blockIdx.z;
    const int q0 = qb * 128;

    const float* Qb = qh + ((size_t)(b * SQL + q0)) * DMODEL + hd * HDIM;
    const float* Kb = kb + ((size_t)b * SQL) * DMODEL + hd * HDIM;
    const float* Vb = vb + ((size_t)b * SQL) * DMODEL + hd * HDIM;

    unsigned sQPa = (unsigned)__cvta_generic_to_shared(sQP);
    unsigned sKa  = (unsigned)__cvta_generic_to_shared(sK);
    unsigned sVa  = (unsigned)__cvta_generic_to_shared(sV);

    // ---- stage Q via cp.async (group 0): 128 rows x 64 floats ----
    {
        int r = t >> 2;                // 0..127
        int cg = (t & 3) * 64;         // byte group base within 256B row
        const char* src = (const char*)(Qb + (size_t)r * DMODEL) + cg;
        unsigned dst = sQPa + r * 272 + cg;
        #pragma unroll
        for (int i = 0; i < 4; i++) cp16(dst + i * 16, src + i * 16);
    }
    CP_COMMIT();

    // ---- stage K/V tile 0 via cp.async (group 1) ----
    const int kr_ = t >> 3;            // 0..63
    const int kc_ = (t & 7) * 32;      // byte offset within 256B row
    {
        const char* ks = (const char*)(Kb + (size_t)kr_ * DMODEL) + kc_;
        const char* vs = (const char*)(Vb + (size_t)kr_ * DMODEL) + kc_;
        unsigned kd = sKa + kr_ * 272 + kc_;
        unsigned vd = sVa + kr_ * 288 + kc_;
        cp16(kd, ks); cp16(kd + 16, ks + 16);
        cp16(vd, vs); cp16(vd + 16, vs + 16);
    }
    CP_COMMIT();

    CP_WAIT(1);                        // Q group done
    __syncthreads();

    // ---- persistent Q A-fragments (one 16-row m-tile) ----
    unsigned qf[8][4];
    {
        int r = mw * 16 + (lane >> 2);
        #pragma unroll
        for (int kk = 0; kk < 8; kk++) {
            int c = kk * 8 + (lane & 3);
            qf[kk][0] = __float_as_uint(sQP[r * 68 + c]);
            qf[kk][1] = __float_as_uint(sQP[(r + 8) * 68 + c]);
            qf[kk][2] = __float_as_uint(sQP[r * 68 + c + 4]);
            qf[kk][3] = __float_as_uint(sQP[(r + 8) * 68 + c + 4]);
        }
    }

    float oacc[4][4];
    #pragma unroll
    for (int ni = 0; ni < 4; ni++)
        #pragma unroll
        for (int r = 0; r < 4; r++) oacc[ni][r] = 0.0f;

    const int jmax = 2 * qb + 1;

    for (int j = 0; j <= jmax; j++) {
        int buf = j & 1;
        // issue next tile into buf^1 (that buffer's readers finished at the
        // end-barrier of iter j-1)
        if (j < jmax) {
            int k0n = (j + 1) * 64;
            const char* ks = (const char*)(Kb + (size_t)(k0n + kr_) * DMODEL) + kc_;
            const char* vs = (const char*)(Vb + (size_t)(k0n + kr_) * DMODEL) + kc_;
            unsigned kd = sKa + (buf ^ 1) * 17408 + kr_ * 272 + kc_;
            unsigned vd = sVa + (buf ^ 1) * 18432 + kr_ * 288 + kc_;
            cp16(kd, ks); cp16(kd + 16, ks + 16);
            cp16(vd, vs); cp16(vd + 16, vs + 16);
            CP_COMMIT();
            CP_WAIT(1);                // tile j complete (next may be pending)
        } else {
            CP_WAIT(0);
        }
        __syncthreads();               // tile j visible; qf loads done (j=0)

        const float* bK = sK + buf * (64 * 68);
        const float* bV = sV + buf * (64 * 72);

        // ---- S = Q K^T on this warp's 32-wide n-half ----
        float sfr[4][4];
        #pragma unroll
        for (int ni = 0; ni < 4; ni++)
            #pragma unroll
            for (int r = 0; r < 4; r++) sfr[ni][r] = 0.0f;
        #pragma unroll
        for (int kk = 0; kk < 8; kk++) {
            #pragma unroll
            for (int ni = 0; ni < 4; ni++) {
                int cb = h * 32 + ni * 8 + (lane >> 2);
                int kr = kk * 8 + (lane & 3);
                unsigned bbf[2];
                bbf[0] = __float_as_uint(bK[cb * 68 + kr]);
                bbf[1] = __float_as_uint(bK[cb * 68 + kr + 4]);
                mma_tf32(sfr[ni], qf[kk], bbf);
            }
        }

        // ---- sigmoid + causal mask -> P (tf32) into sQP ----
        {
            int r = mw * 16 + (lane >> 2);
            int g0 = q0 + r, g1 = g0 + 8;
            #pragma unroll
            for (int ni = 0; ni < 4; ni++) {
                int c  = h * 32 + ni * 8 + 2 * (lane & 3);
                int gc = j * 64 + c;
                float p00 = __fdividef(1.f, 1.f + __expf(8.f - sfr[ni][0] * 0.125f));
                float p01 = __fdividef(1.f, 1.f + __expf(8.f - sfr[ni][1] * 0.125f));
                float p10 = __fdividef(1.f, 1.f + __expf(8.f - sfr[ni][2] * 0.125f));
                float p11 = __fdividef(1.f, 1.f + __expf(8.f - sfr[ni][3] * 0.125f));
                p00 = (gc     <= g0) ? p00 : 0.f;
                p01 = (gc + 1 <= g0) ? p01 : 0.f;
                p10 = (gc     <= g1) ? p10 : 0.f;
                p11 = (gc + 1 <= g1) ? p11 : 0.f;
                sQP[r * 68 + c]           = f2tf32(p00);
                sQP[r * 68 + c + 1]       = f2tf32(p01);
                sQP[(r + 8) * 68 + c]     = f2tf32(p10);
                sQP[(r + 8) * 68 + c + 1] = f2tf32(p11);
            }
        }
        __syncthreads();               // full P tile visible

        // ---- O += P V on this warp's 32-wide d-half ----
        #pragma unroll
        for (int kk = 0; kk < 8; kk++) {
            int r = mw * 16 + (lane >> 2);
            int c = kk * 8 + (lane & 3);
            unsigned pf[4];
            pf[0] = __float_as_uint(sQP[r * 68 + c]);
            pf[1] = __float_as_uint(sQP[(r + 8) * 68 + c]);
            pf[2] = __float_as_uint(sQP[r * 68 + c + 4]);
            pf[3] = __float_as_uint(sQP[(r + 8) * 68 + c + 4]);
            #pragma unroll
            for (int ni = 0; ni < 4; ni++) {
                int cb = h * 32 + ni * 8 + (lane >> 2);
                int kr = kk * 8 + (lane & 3);
                unsigned bbf[2];
                bbf[0] = __float_as_uint(bV[kr * 72 + cb]);
                bbf[1] = __float_as_uint(bV[(kr + 4) * 72 + cb]);
                mma_tf32(oacc[ni], pf, bbf);
            }
        }
        __syncthreads();               // buf readers done; sQP reusable
    }

    // ---- epilogue ----
    {
        int r = mw * 16 + (lane >> 2);
        float* ob = out + ((size_t)(b * SQL + q0 + r)) * DMODEL + hd * HDIM;
        #pragma unroll
        for (int ni = 0; ni < 4; ni++) {
            int c = h * 32 + ni * 8 + 2 * (lane & 3);
            *(float2*)(ob + c) = make_float2(oacc[ni][0], oacc[ni][1]);
            *(float2*)(ob + (size_t)8 * DMODEL + c) =
                make_float2(oacc[ni][2], oacc[ni][3]);
        }
    }
}

#define ATTN_SMEM ((128 * 68 + 2 * 64 * 68 + 2 * 64 * 72) * 4)   // 106496 B

// ---------------------------------------------------------------------------
extern "C" void kernel_launch(void* const* d_in, const int* in_sizes, int n_in,
                              void* d_out, int out_size)
{
    const float* q     = (const float*)d_in[0];
    const float* kv    = (const float*)d_in[1];
    const float* Wq    = (const float*)d_in[2];
    const float* Wkv   = (const float*)d_in[3];
    const float* gamma = (const float*)d_in[4];
    const float* beta  = (const float*)d_in[5];
    const float* Wproj = (const float*)d_in[6];
    float* out = (float*)d_out;

    float *qh, *kbuf, *vbuf;
    cudaGetSymbolAddress((void**)&qh,   g_qh);
    cudaGetSymbolAddress((void**)&kbuf, g_k);
    cudaGetSymbolAddress((void**)&vbuf, g_v);

    cudaFuncSetAttribute(attn_tc,
        cudaFuncAttributeMaxDynamicSharedMemorySize, ATTN_SMEM);

    const int M = NB * SQL;   // 4096

    // 1) qh = q @ Wq  (tf32-rounded output: feeds attention mma)
    gemm_tc<<<dim3(DMODEL / 128, M / 128), 256>>>(
        q, Wq, qh, nullptr, M, DMODEL, DMODEL, DMODEL, 1);

    // 2) kvh = kv @ Wkv, split K / V (tf32-rounded: feed attention mma)
    gemm_tc<<<dim3(2 * DMODEL / 128, M / 128), 256>>>(
        kv, Wkv, kbuf, vbuf, M, 2 * DMODEL, DMODEL, DMODEL, 1);

    // 3) per-head LayerNorm of V (writes tf32)
    ln64<<<(NB * SQL * NH) / 8, 256>>>(vbuf, gamma, beta);

    // 4) attention -> attn_times_v (first half of d_out, fp32)
    attn_tc<<<dim3(SQL / 128, NH, NB), 512, ATTN_SMEM>>>(qh, kbuf, vbuf, out);

    // 5) attn_proj = attn_times_v @ Wproj (second half of d_out, fp32)
    gemm_tc<<<dim3(DMODEL / 128, M / 128), 256>>>(
        out, Wproj, out + (size_t)M * DMODEL, nullptr, M, DMODEL, DMODEL, DMODEL, 0);
}